// round 1
// baseline (speedup 1.0000x reference)
#include <cuda_runtime.h>

// LinearAttention: out[n,l,h,e] = (phi(Q)@KV) * Z * vlen, phi = elu+1
//   KV  = sum_s phi(K)[s,d] * (V/vlen)[s,e]   ; vlen cancels -> use raw V
//   Z   = 1 / (phi(Q) . sum_s phi(K) + 1e-6)
//
// Phase 1: per (n,h) x S-chunk, accumulate partial KV[64x64] + Ksum[64] in
//          registers (fp32x2 packed FMA), write partials (deterministic).
// Phase 1b: fixed-order reduction of 16 partials.
// Phase 2: per (n,h) x 128-l tile: out = (phiQ @ KV) * Z. Q transposed into
//          smem in 16-d chunks; KV/Ksum stay L1-resident via __ldg.

#define DEV_INLINE __device__ __forceinline__

constexpr int Hh = 8, Dd = 64, Ll = 8192, Ss = 8192, Nn = 4;
constexpr int NH = Nn * Hh;              // 32
constexpr int ROWSTRIDE = Hh * Dd;       // 512 floats between consecutive s (or l)
constexpr int P1_CHUNKS = 16;
constexpr int P1_SCHUNK = Ss / P1_CHUNKS; // 512
constexpr int TS = 32;                    // s-rows staged per smem tile
constexpr int P1_NTILES = P1_SCHUNK / TS; // 16
constexpr int P2_TL = 128;                // l-rows per phase-2 block
constexpr int PADL = 132;                 // padded l-row for transposed Q smem

// Scratch (static device arrays: no allocation anywhere)
__device__ __align__(16) float g_part_kv[P1_CHUNKS * NH * 64 * 64]; // 8 MB
__device__ __align__(16) float g_part_ks[P1_CHUNKS * NH * 64];
__device__ __align__(16) float g_kv[NH * 64 * 64];
__device__ __align__(16) float g_ks[NH * 64];

using u64 = unsigned long long;

DEV_INLINE u64 pk2(float lo, float hi) {
    u64 r; asm("mov.b64 %0,{%1,%2};" : "=l"(r) : "f"(lo), "f"(hi)); return r;
}
DEV_INLINE void upk2(u64 v, float& a, float& b) {
    asm("mov.b64 {%0,%1},%2;" : "=f"(a), "=f"(b) : "l"(v));
}
DEV_INLINE u64 ffma2(u64 a, u64 b, u64 c) {
    u64 d; asm("fma.rn.f32x2 %0,%1,%2,%3;" : "=l"(d) : "l"(a), "l"(b), "l"(c)); return d;
}
DEV_INLINE u64 fadd2(u64 a, u64 b) {
    u64 d; asm("add.rn.f32x2 %0,%1,%2;" : "=l"(d) : "l"(a), "l"(b)); return d;
}
DEV_INLINE u64 fmul2(u64 a, u64 b) {
    u64 d; asm("mul.rn.f32x2 %0,%1,%2;" : "=l"(d) : "l"(a), "l"(b)); return d;
}

// elu(x)+1 == exp(min(x,0)) + max(x,0), branchless (single MUFU)
DEV_INLINE float featmap(float x) { return __expf(fminf(x, 0.f)) + fmaxf(x, 0.f); }

// ============================================================================
// Phase 1: KV partials. Block = 128 thr, tile 64d x 64e, thread = 4d x 8e.
// Grid: (P1_CHUNKS, NH)
// ============================================================================
__global__ __launch_bounds__(128) void p1_kernel(const float* __restrict__ keys,
                                                 const float* __restrict__ values) {
    __shared__ float Ks[TS][64];
    __shared__ float Vs[TS][64];

    const int t  = threadIdx.x;
    const int nh = blockIdx.y;
    const int n  = nh >> 3, h = nh & 7;
    const int s0 = blockIdx.x * P1_SCHUNK;
    const int ty = t >> 3;   // 0..15 -> d-group of 4
    const int tx = t & 7;    // 0..7  -> e-group {tx*4..+3} u {tx*4+32..+35}

    u64 acc[4][4];
#pragma unroll
    for (int i = 0; i < 4; i++)
#pragma unroll
        for (int j = 0; j < 4; j++) acc[i][j] = 0ull;
    u64 ks0 = 0ull, ks1 = 0ull;

    // loader slots: j = t + 128k -> row = j>>4 (0..31), c = j&15 (float4 col)
    int rr[4], cc[4];
#pragma unroll
    for (int k = 0; k < 4; k++) { int j = t + 128 * k; rr[k] = j >> 4; cc[k] = j & 15; }

    float4 bk[4], bv[4];

    // --- prefetch tile 0 ---
#pragma unroll
    for (int k = 0; k < 4; k++) {
        size_t row = (size_t)(n * Ss + s0 + rr[k]);
        bk[k] = *(const float4*)(keys   + row * ROWSTRIDE + h * Dd + cc[k] * 4);
        bv[k] = *(const float4*)(values + row * ROWSTRIDE + h * Dd + cc[k] * 4);
    }
#pragma unroll
    for (int k = 0; k < 4; k++) {
        float4 f;
        f.x = featmap(bk[k].x); f.y = featmap(bk[k].y);
        f.z = featmap(bk[k].z); f.w = featmap(bk[k].w);
        *(float4*)&Ks[rr[k]][cc[k] * 4] = f;
        *(float4*)&Vs[rr[k]][cc[k] * 4] = bv[k];
    }
    __syncthreads();

    for (int tile = 0; tile < P1_NTILES; ++tile) {
        if (tile + 1 < P1_NTILES) {
#pragma unroll
            for (int k = 0; k < 4; k++) {
                size_t row = (size_t)(n * Ss + s0 + (tile + 1) * TS + rr[k]);
                bk[k] = *(const float4*)(keys   + row * ROWSTRIDE + h * Dd + cc[k] * 4);
                bv[k] = *(const float4*)(values + row * ROWSTRIDE + h * Dd + cc[k] * 4);
            }
        }
#pragma unroll 8
        for (int ss = 0; ss < TS; ++ss) {
            float4 k4 = *(const float4*)&Ks[ss][ty * 4];
            float4 va = *(const float4*)&Vs[ss][tx * 4];
            float4 vb = *(const float4*)&Vs[ss][tx * 4 + 32];
            u64 vp[4] = { pk2(va.x, va.y), pk2(va.z, va.w),
                          pk2(vb.x, vb.y), pk2(vb.z, vb.w) };
            float kd[4] = { k4.x, k4.y, k4.z, k4.w };
#pragma unroll
            for (int d = 0; d < 4; ++d) {
                u64 kk = pk2(kd[d], kd[d]);
#pragma unroll
                for (int e = 0; e < 4; ++e) acc[d][e] = ffma2(kk, vp[e], acc[d][e]);
            }
            if (tx == 0) {
                ks0 = fadd2(ks0, pk2(k4.x, k4.y));
                ks1 = fadd2(ks1, pk2(k4.z, k4.w));
            }
        }
        __syncthreads();
        if (tile + 1 < P1_NTILES) {
#pragma unroll
            for (int k = 0; k < 4; k++) {
                float4 f;
                f.x = featmap(bk[k].x); f.y = featmap(bk[k].y);
                f.z = featmap(bk[k].z); f.w = featmap(bk[k].w);
                *(float4*)&Ks[rr[k]][cc[k] * 4] = f;
                *(float4*)&Vs[rr[k]][cc[k] * 4] = bv[k];
            }
            __syncthreads();
        }
    }

    // write per-chunk partials (deterministic, no atomics)
    float* outp = g_part_kv + ((size_t)blockIdx.x * NH + nh) * 4096;
#pragma unroll
    for (int d = 0; d < 4; ++d) {
        int dg = ty * 4 + d;
        u64* row = (u64*)(outp + dg * 64);
        row[tx * 2 + 0]  = acc[d][0];
        row[tx * 2 + 1]  = acc[d][1];
        row[tx * 2 + 16] = acc[d][2];
        row[tx * 2 + 17] = acc[d][3];
    }
    if (tx == 0) {
        u64* kso = (u64*)(g_part_ks + ((size_t)blockIdx.x * NH + nh) * 64 + ty * 4);
        kso[0] = ks0; kso[1] = ks1;
    }
}

// ============================================================================
// Phase 1b: fixed-order reduction of the 16 partials
// ============================================================================
__global__ void reduce_kernel() {
    int i = blockIdx.x * blockDim.x + threadIdx.x;
    if (i < NH * 4096) {
        float s = 0.f;
#pragma unroll
        for (int c = 0; c < P1_CHUNKS; c++) s += g_part_kv[(size_t)c * NH * 4096 + i];
        g_kv[i] = s;
    } else if (i < NH * 4096 + NH * 64) {
        int j = i - NH * 4096;
        float s = 0.f;
#pragma unroll
        for (int c = 0; c < P1_CHUNKS; c++) s += g_part_ks[c * NH * 64 + j];
        g_ks[j] = s;
    }
}

// ============================================================================
// Phase 2: out tile 128l x 64e per block (128 thr), thread = 8l x 8e.
// Grid: (Ll/P2_TL, NH)
// ============================================================================
__global__ __launch_bounds__(128) void p2_kernel(const float* __restrict__ queries,
                                                 float* __restrict__ out) {
    __shared__ float Qs[16][PADL];   // transposed chunk: Qs[d_local][l_local]

    const int t  = threadIdx.x;
    const int nh = blockIdx.y;
    const int n  = nh >> 3, h = nh & 7;
    const int l0 = blockIdx.x * P2_TL;
    const int ty = t >> 3;   // 0..15 -> l-group {ty*4..+3} u {ty*4+64..+67}
    const int tx = t & 7;    // 0..7  -> e-group {tx*4..+3} u {tx*4+32..+35}

    u64 acc[2][4][4];
#pragma unroll
    for (int g = 0; g < 2; g++)
#pragma unroll
        for (int i = 0; i < 4; i++)
#pragma unroll
            for (int e = 0; e < 4; e++) acc[g][i][e] = 0ull;
    u64 z2[2][2] = { {0ull, 0ull}, {0ull, 0ull} };

    // loader slots: j = t + 128k -> l = j>>2 (0..127), c = j&3 (float4 of the 16-d chunk)
    int lr[4], lc[4];
#pragma unroll
    for (int k = 0; k < 4; k++) { int j = t + 128 * k; lr[k] = j >> 2; lc[k] = j & 3; }

    const float* kvbase = g_kv + (size_t)nh * 4096;
    const float* ksbase = g_ks + nh * 64;

    float4 bq[4];
    // --- prefetch + stage chunk 0 ---
#pragma unroll
    for (int k = 0; k < 4; k++) {
        size_t row = (size_t)(n * Ll + l0 + lr[k]);
        bq[k] = *(const float4*)(queries + row * ROWSTRIDE + h * Dd + lc[k] * 4);
    }
#pragma unroll
    for (int k = 0; k < 4; k++) {
        int dbase = lc[k] * 4, l = lr[k];
        Qs[dbase + 0][l] = featmap(bq[k].x);
        Qs[dbase + 1][l] = featmap(bq[k].y);
        Qs[dbase + 2][l] = featmap(bq[k].z);
        Qs[dbase + 3][l] = featmap(bq[k].w);
    }
    __syncthreads();

    for (int ch = 0; ch < 4; ++ch) {
        if (ch + 1 < 4) {
#pragma unroll
            for (int k = 0; k < 4; k++) {
                size_t row = (size_t)(n * Ll + l0 + lr[k]);
                bq[k] = *(const float4*)(queries + row * ROWSTRIDE + h * Dd +
                                         (ch + 1) * 16 + lc[k] * 4);
            }
        }
#pragma unroll 4
        for (int dd = 0; dd < 16; ++dd) {
            int d = ch * 16 + dd;
            float4 qa = *(const float4*)&Qs[dd][ty * 4];
            float4 qb = *(const float4*)&Qs[dd][ty * 4 + 64];
            float4 kva = __ldg((const float4*)(kvbase + d * 64 + tx * 4));
            float4 kvb = __ldg((const float4*)(kvbase + d * 64 + tx * 4 + 32));
            float  ksd = __ldg(ksbase + d);
            u64 vp[4] = { pk2(kva.x, kva.y), pk2(kva.z, kva.w),
                          pk2(kvb.x, kvb.y), pk2(kvb.z, kvb.w) };
            u64 kk = pk2(ksd, ksd);
            float qav[4] = { qa.x, qa.y, qa.z, qa.w };
            float qbv[4] = { qb.x, qb.y, qb.z, qb.w };
#pragma unroll
            for (int i = 0; i < 4; ++i) {
                u64 qq = pk2(qav[i], qav[i]);
#pragma unroll
                for (int e = 0; e < 4; ++e) acc[0][i][e] = ffma2(qq, vp[e], acc[0][i][e]);
            }
#pragma unroll
            for (int i = 0; i < 4; ++i) {
                u64 qq = pk2(qbv[i], qbv[i]);
#pragma unroll
                for (int e = 0; e < 4; ++e) acc[1][i][e] = ffma2(qq, vp[e], acc[1][i][e]);
            }
            z2[0][0] = ffma2(pk2(qa.x, qa.y), kk, z2[0][0]);
            z2[0][1] = ffma2(pk2(qa.z, qa.w), kk, z2[0][1]);
            z2[1][0] = ffma2(pk2(qb.x, qb.y), kk, z2[1][0]);
            z2[1][1] = ffma2(pk2(qb.z, qb.w), kk, z2[1][1]);
        }
        __syncthreads();
        if (ch + 1 < 4) {
#pragma unroll
            for (int k = 0; k < 4; k++) {
                int dbase = lc[k] * 4, l = lr[k];
                Qs[dbase + 0][l] = featmap(bq[k].x);
                Qs[dbase + 1][l] = featmap(bq[k].y);
                Qs[dbase + 2][l] = featmap(bq[k].z);
                Qs[dbase + 3][l] = featmap(bq[k].w);
            }
            __syncthreads();
        }
    }

    // epilogue: out = acc * 1/(z + eps)   (vlen cancels: raw-V KV)
#pragma unroll
    for (int g = 0; g < 2; ++g) {
        float zv[4];
        upk2(z2[g][0], zv[0], zv[1]);
        upk2(z2[g][1], zv[2], zv[3]);
#pragma unroll
        for (int i = 0; i < 4; ++i) {
            int l = l0 + ty * 4 + g * 64 + i;
            float inv = 1.0f / (zv[i] + 1e-6f);
            u64 iv = pk2(inv, inv);
            u64* orow = (u64*)(out + ((size_t)(n * Ll + l) * Hh + h) * Dd);
            orow[tx * 2 + 0]  = fmul2(acc[g][i][0], iv);
            orow[tx * 2 + 1]  = fmul2(acc[g][i][1], iv);
            orow[tx * 2 + 16] = fmul2(acc[g][i][2], iv);
            orow[tx * 2 + 17] = fmul2(acc[g][i][3], iv);
        }
    }
}

// ============================================================================
extern "C" void kernel_launch(void* const* d_in, const int* in_sizes, int n_in,
                              void* d_out, int out_size) {
    const float* q = (const float*)d_in[0];
    const float* k = (const float*)d_in[1];
    const float* v = (const float*)d_in[2];
    float* o = (float*)d_out;
    (void)in_sizes; (void)n_in; (void)out_size;

    p1_kernel<<<dim3(P1_CHUNKS, NH), 128>>>(k, v);
    reduce_kernel<<<(NH * 4096 + NH * 64 + 255) / 256, 256>>>();
    p2_kernel<<<dim3(Ll / P2_TL, NH), 128>>>(q, o);
}

// round 2
// speedup vs baseline: 1.0341x; 1.0341x over previous
#include <cuda_runtime.h>

// LinearAttention: out[n,l,h,e] = (phi(Q)@KV) * Z, phi = elu+1 (vlen cancels)
//   KV  = sum_s phi(K)[s,d] * V[s,e]
//   Z   = 1 / (phi(Q) . Ksum + 1e-6), Ksum = sum_s phi(K)
//
// R1: 256-thr blocks, pre-packed smem operands (dup-pairs for broadcast scalars,
// natural ulonglong2 for vectors) -> zero packing MOVs in inner loops; p2 KV in
// smem; higher occupancy.

#define DEV_INLINE __device__ __forceinline__

constexpr int Hh = 8, Dd = 64, Ll = 8192, Ss = 8192, Nn = 4;
constexpr int NH = Nn * Hh;               // 32
constexpr int ROWSTRIDE = Hh * Dd;        // 512
constexpr int P1_CHUNKS = 32;
constexpr int P1_SCHUNK = Ss / P1_CHUNKS; // 256
constexpr int TS = 32;
constexpr int P1_NTILES = P1_SCHUNK / TS; // 8
constexpr int P2_TL = 128;

__device__ __align__(16) float g_part_kv[P1_CHUNKS * NH * 64 * 64]; // 16 MB
__device__ __align__(16) float g_part_ks[P1_CHUNKS * NH * 64];
__device__ __align__(16) float g_kv[NH * 64 * 64];
__device__ __align__(16) float g_ks[NH * 64];

using u64 = unsigned long long;

DEV_INLINE u64 pk2(float lo, float hi) {
    u64 r; asm("mov.b64 %0,{%1,%2};" : "=l"(r) : "f"(lo), "f"(hi)); return r;
}
DEV_INLINE float lo2(u64 v) {
    float a, b; asm("mov.b64 {%0,%1},%2;" : "=f"(a), "=f"(b) : "l"(v)); return a;
}
DEV_INLINE u64 ffma2(u64 a, u64 b, u64 c) {
    u64 d; asm("fma.rn.f32x2 %0,%1,%2,%3;" : "=l"(d) : "l"(a), "l"(b), "l"(c)); return d;
}
DEV_INLINE u64 fmul2(u64 a, u64 b) {
    u64 d; asm("mul.rn.f32x2 %0,%1,%2;" : "=l"(d) : "l"(a), "l"(b)); return d;
}
DEV_INLINE u64 dup(float x) { return pk2(x, x); }

// elu(x)+1 == exp(min(x,0)) + max(x,0)
DEV_INLINE float featmap(float x) { return __expf(fminf(x, 0.f)) + fmaxf(x, 0.f); }

// ============================================================================
// Phase 1: 256 thr, tile 64d x 64e, thread = 4d x 4e. Grid (P1_CHUNKS, NH).
// Kd holds duplicated phi(K) pairs; Vs natural floats.
// ============================================================================
__global__ __launch_bounds__(256) void p1_kernel(const float* __restrict__ keys,
                                                 const float* __restrict__ values) {
    __shared__ __align__(16) u64   Kd[TS][66];   // [s][d] dup pairs
    __shared__ __align__(16) float Vs[TS][68];   // [s][e]

    const int t  = threadIdx.x;
    const int nh = blockIdx.y;
    const int n  = nh >> 3, h = nh & 7;
    const int s0 = blockIdx.x * P1_SCHUNK;
    const int ty = t >> 4;   // 0..15 -> d-group ty*4
    const int tx = t & 15;   // 0..15 -> e-group tx*4

    u64 acc[4][2];
#pragma unroll
    for (int i = 0; i < 4; i++) { acc[i][0] = 0ull; acc[i][1] = 0ull; }
    float ksum = 0.f;  // valid for t < 64 (d = t)

    // loader slots: j = t + 256k (k=0,1) -> row j>>4 (0..31), col j&15
    int rr[2], cc[2];
#pragma unroll
    for (int k = 0; k < 2; k++) { int j = t + 256 * k; rr[k] = j >> 4; cc[k] = j & 15; }

    float4 bk[2], bv[2];
#pragma unroll
    for (int k = 0; k < 2; k++) {
        size_t row = (size_t)(n * Ss + s0 + rr[k]);
        bk[k] = *(const float4*)(keys   + row * ROWSTRIDE + h * Dd + cc[k] * 4);
        bv[k] = *(const float4*)(values + row * ROWSTRIDE + h * Dd + cc[k] * 4);
    }
#pragma unroll
    for (int k = 0; k < 2; k++) {
        ulonglong2* kd = (ulonglong2*)&Kd[rr[k]][cc[k] * 4];
        kd[0] = make_ulonglong2(dup(featmap(bk[k].x)), dup(featmap(bk[k].y)));
        kd[1] = make_ulonglong2(dup(featmap(bk[k].z)), dup(featmap(bk[k].w)));
        *(float4*)&Vs[rr[k]][cc[k] * 4] = bv[k];
    }
    __syncthreads();

    for (int tile = 0; tile < P1_NTILES; ++tile) {
        if (tile + 1 < P1_NTILES) {
#pragma unroll
            for (int k = 0; k < 2; k++) {
                size_t row = (size_t)(n * Ss + s0 + (tile + 1) * TS + rr[k]);
                bk[k] = *(const float4*)(keys   + row * ROWSTRIDE + h * Dd + cc[k] * 4);
                bv[k] = *(const float4*)(values + row * ROWSTRIDE + h * Dd + cc[k] * 4);
            }
        }
#pragma unroll 8
        for (int ss = 0; ss < TS; ++ss) {
            ulonglong2 ka = *(const ulonglong2*)&Kd[ss][ty * 4];
            ulonglong2 kb = *(const ulonglong2*)&Kd[ss][ty * 4 + 2];
            ulonglong2 vv = *(const ulonglong2*)&Vs[ss][tx * 4];
            u64 kk[4] = { ka.x, ka.y, kb.x, kb.y };
#pragma unroll
            for (int d = 0; d < 4; ++d) {
                acc[d][0] = ffma2(kk[d], vv.x, acc[d][0]);
                acc[d][1] = ffma2(kk[d], vv.y, acc[d][1]);
            }
        }
        // Ksum: column sum of this tile's phi(K) (low halves of dup pairs)
        if (t < 64) {
#pragma unroll 8
            for (int ss = 0; ss < TS; ++ss) ksum += *(const float*)&Kd[ss][t];
        }
        __syncthreads();
        if (tile + 1 < P1_NTILES) {
#pragma unroll
            for (int k = 0; k < 2; k++) {
                ulonglong2* kd = (ulonglong2*)&Kd[rr[k]][cc[k] * 4];
                kd[0] = make_ulonglong2(dup(featmap(bk[k].x)), dup(featmap(bk[k].y)));
                kd[1] = make_ulonglong2(dup(featmap(bk[k].z)), dup(featmap(bk[k].w)));
                *(float4*)&Vs[rr[k]][cc[k] * 4] = bv[k];
            }
            __syncthreads();
        }
    }

    // write partials (deterministic)
    float* outp = g_part_kv + ((size_t)blockIdx.x * NH + nh) * 4096;
#pragma unroll
    for (int d = 0; d < 4; ++d) {
        int dg = ty * 4 + d;
        *(ulonglong2*)(outp + dg * 64 + tx * 4) = make_ulonglong2(acc[d][0], acc[d][1]);
    }
    if (t < 64) g_part_ks[((size_t)blockIdx.x * NH + nh) * 64 + t] = ksum;
}

// ============================================================================
// Phase 1b: fixed-order reduction of the partials
// ============================================================================
__global__ void reduce_kernel() {
    int i = blockIdx.x * blockDim.x + threadIdx.x;
    if (i < NH * 4096) {
        float s = 0.f;
#pragma unroll
        for (int c = 0; c < P1_CHUNKS; c++) s += g_part_kv[(size_t)c * NH * 4096 + i];
        g_kv[i] = s;
    } else if (i < NH * 4096 + NH * 64) {
        int j = i - NH * 4096;
        float s = 0.f;
#pragma unroll
        for (int c = 0; c < P1_CHUNKS; c++) s += g_part_ks[c * NH * 64 + j];
        g_ks[j] = s;
    }
}

// ============================================================================
// Phase 2: 256 thr, tile 128l x 64e, thread = 4l x 8e. Grid (Ll/128, NH).
// KV + dup-Ksum resident in smem; Q staged as duplicated pairs per 16-d chunk.
// ============================================================================
__global__ __launch_bounds__(256) void p2_kernel(const float* __restrict__ queries,
                                                 float* __restrict__ out) {
    __shared__ __align__(16) float KVs[64][64];  // [d][e]
    __shared__ __align__(16) u64   Ksd[64];      // dup(Ksum[d])
    __shared__ __align__(16) u64   Qd[16][132];  // [d_local][l] dup(phi(Q))

    const int t  = threadIdx.x;
    const int nh = blockIdx.y;
    const int n  = nh >> 3, h = nh & 7;
    const int l0 = blockIdx.x * P2_TL;
    const int ty = t >> 3;   // 0..31 -> l-group ty*4
    const int tx = t & 7;    // 0..7  -> e-groups {tx*4, tx*4+32}

    // load KV + Ksum into smem
    {
        const float* kvbase = g_kv + (size_t)nh * 4096;
#pragma unroll
        for (int k = 0; k < 4; k++) {
            int j = t + 256 * k;
            int row = j >> 4, col = j & 15;
            *(float4*)&KVs[row][col * 4] = *(const float4*)(kvbase + row * 64 + col * 4);
        }
        if (t < 64) Ksd[t] = dup(g_ks[nh * 64 + t]);
    }

    u64 acc[4][4];
#pragma unroll
    for (int i = 0; i < 4; i++)
#pragma unroll
        for (int e = 0; e < 4; e++) acc[i][e] = 0ull;
    u64 z2[4] = { 0ull, 0ull, 0ull, 0ull };

    // Q loader slots: j = t + 256k (k=0,1) -> l = j>>2 (0..127), c = j&3
    int lr[2], lc[2];
#pragma unroll
    for (int k = 0; k < 2; k++) { int j = t + 256 * k; lr[k] = j >> 2; lc[k] = j & 3; }

    float4 bq[2];
#pragma unroll
    for (int k = 0; k < 2; k++) {
        size_t row = (size_t)(n * Ll + l0 + lr[k]);
        bq[k] = *(const float4*)(queries + row * ROWSTRIDE + h * Dd + lc[k] * 4);
    }
    __syncthreads();   // covers KV load AND Qd about to be written
#pragma unroll
    for (int k = 0; k < 2; k++) {
        int db = lc[k] * 4, l = lr[k];
        Qd[db + 0][l] = dup(featmap(bq[k].x));
        Qd[db + 1][l] = dup(featmap(bq[k].y));
        Qd[db + 2][l] = dup(featmap(bq[k].z));
        Qd[db + 3][l] = dup(featmap(bq[k].w));
    }
    __syncthreads();

    for (int ch = 0; ch < 4; ++ch) {
        if (ch + 1 < 4) {
#pragma unroll
            for (int k = 0; k < 2; k++) {
                size_t row = (size_t)(n * Ll + l0 + lr[k]);
                bq[k] = *(const float4*)(queries + row * ROWSTRIDE + h * Dd +
                                         (ch + 1) * 16 + lc[k] * 4);
            }
        }
#pragma unroll 4
        for (int dd = 0; dd < 16; ++dd) {
            int d = ch * 16 + dd;
            ulonglong2 qa = *(const ulonglong2*)&Qd[dd][ty * 4];
            ulonglong2 qb = *(const ulonglong2*)&Qd[dd][ty * 4 + 2];
            ulonglong2 va = *(const ulonglong2*)&KVs[d][tx * 4];
            ulonglong2 vb = *(const ulonglong2*)&KVs[d][tx * 4 + 32];
            u64 ks2 = Ksd[d];
            u64 qq[4] = { qa.x, qa.y, qb.x, qb.y };
            u64 vp[4] = { va.x, va.y, vb.x, vb.y };
#pragma unroll
            for (int i = 0; i < 4; ++i) {
                acc[i][0] = ffma2(qq[i], vp[0], acc[i][0]);
                acc[i][1] = ffma2(qq[i], vp[1], acc[i][1]);
                acc[i][2] = ffma2(qq[i], vp[2], acc[i][2]);
                acc[i][3] = ffma2(qq[i], vp[3], acc[i][3]);
                z2[i]     = ffma2(qq[i], ks2,   z2[i]);
            }
        }
        __syncthreads();
        if (ch + 1 < 4) {
#pragma unroll
            for (int k = 0; k < 2; k++) {
                int db = lc[k] * 4, l = lr[k];
                Qd[db + 0][l] = dup(featmap(bq[k].x));
                Qd[db + 1][l] = dup(featmap(bq[k].y));
                Qd[db + 2][l] = dup(featmap(bq[k].z));
                Qd[db + 3][l] = dup(featmap(bq[k].w));
            }
            __syncthreads();
        }
    }

    // epilogue: out = acc / (z + eps)
#pragma unroll
    for (int i = 0; i < 4; ++i) {
        int l = l0 + ty * 4 + i;
        float inv = 1.0f / (lo2(z2[i]) + 1e-6f);
        u64 iv = dup(inv);
        u64* orow = (u64*)(out + ((size_t)(n * Ll + l) * Hh + h) * Dd);
        *(ulonglong2*)&orow[tx * 2]      = make_ulonglong2(fmul2(acc[i][0], iv),
                                                           fmul2(acc[i][1], iv));
        *(ulonglong2*)&orow[tx * 2 + 16] = make_ulonglong2(fmul2(acc[i][2], iv),
                                                           fmul2(acc[i][3], iv));
    }
}

// ============================================================================
extern "C" void kernel_launch(void* const* d_in, const int* in_sizes, int n_in,
                              void* d_out, int out_size) {
    const float* q = (const float*)d_in[0];
    const float* k = (const float*)d_in[1];
    const float* v = (const float*)d_in[2];
    float* o = (float*)d_out;
    (void)in_sizes; (void)n_in; (void)out_size;

    p1_kernel<<<dim3(P1_CHUNKS, NH), 256>>>(k, v);
    reduce_kernel<<<(NH * 4096 + NH * 64 + 255) / 256, 256>>>();
    p2_kernel<<<dim3(Ll / P2_TL, NH), 256>>>(q, o);
}

// round 3
// speedup vs baseline: 1.3109x; 1.2677x over previous
#include <cuda_runtime.h>

// LinearAttention: out[n,l,h,e] = (phi(Q)@KV) * Z, phi = elu+1 (vlen cancels)
//   KV  = sum_s phi(K)[s,d] * V[s,e] ;  Z = 1/(phi(Q).Ksum + 1e-6)
//
// R3: 8x8 per-thread register tiles, FFMA2 packed accumulators.
//  p1: acc packed along d (K pairs natural from LDS, V dup'd via ALU MOVs),
//      partial KV written transposed [e][d]. 2 warp-pair groups per block
//      work alternate ss-halves (each gets its own partial slot).
//  p2: acc packed along l (Q pairs natural, KV dup'd), Z rides as a 9th "e".
// Per inner step: 4 LDS.128 : 32 FFMA2 (balanced 16:16 SM-cycles, diff pipes).

#define DEV_INLINE __device__ __forceinline__

constexpr int Hh = 8, Dd = 64, Ll = 8192, Ss = 8192, Nn = 4;
constexpr int NH = Nn * Hh;                // 32
constexpr int ROWSTRIDE = Hh * Dd;         // 512
constexpr int P1_CHUNKS = 32;
constexpr int P1_SCHUNK = Ss / P1_CHUNKS;  // 256
constexpr int TS = 16;                     // ss rows per smem tile
constexpr int P1_NTILES = P1_SCHUNK / TS;  // 16
constexpr int SLOTS = P1_CHUNKS * 2;       // 64 (2 groups per block)

// scratch: KV partials stored TRANSPOSED [slot][nh][e][d]
__device__ __align__(16) float g_part_kv[(size_t)SLOTS * NH * 4096]; // 32 MB
__device__ __align__(16) float g_part_ks[SLOTS * NH * 64];
__device__ __align__(16) float g_kv[NH * 4096];   // [nh][e][d]
__device__ __align__(16) float g_ks[NH * 64];

using u64 = unsigned long long;

DEV_INLINE u64 pk2(float lo, float hi) {
    u64 r; asm("mov.b64 %0,{%1,%2};" : "=l"(r) : "f"(lo), "f"(hi)); return r;
}
DEV_INLINE void upk2(u64 v, float& a, float& b) {
    asm("mov.b64 {%0,%1},%2;" : "=f"(a), "=f"(b) : "l"(v));
}
DEV_INLINE u64 ffma2(u64 a, u64 b, u64 c) {
    u64 d; asm("fma.rn.f32x2 %0,%1,%2,%3;" : "=l"(d) : "l"(a), "l"(b), "l"(c)); return d;
}
DEV_INLINE u64 dup(float x) { return pk2(x, x); }

// elu(x)+1 == exp(min(x,0)) + max(x,0)
DEV_INLINE float featmap(float x) { return __expf(fminf(x, 0.f)) + fmaxf(x, 0.f); }

// ============================================================================
// Phase 1. Block = 128 thr = 2 groups of 64. Group g handles ss in
// [g*8, g*8+8) of each 16-ss tile; thread tile 8d x 8e. Grid (P1_CHUNKS, NH).
// ============================================================================
__global__ __launch_bounds__(128, 3) void p1_kernel(const float* __restrict__ keys,
                                                    const float* __restrict__ values) {
    __shared__ __align__(16) float Ks[TS][68];  // phi(K), natural
    __shared__ __align__(16) float Vs[TS][68];

    const int t  = threadIdx.x;
    const int nh = blockIdx.y;
    const int n  = nh >> 3, h = nh & 7;
    const int s0 = blockIdx.x * P1_SCHUNK;
    const int g  = t >> 6;          // group 0/1
    const int tg = t & 63;
    const int ty = tg >> 3;         // 0..7 -> d-base ty*8
    const int tx = tg & 7;          // 0..7 -> e in {tx*4..+3} u {tx*4+32..+35}

    u64 acc[4][8];                  // [d-pair][e]
#pragma unroll
    for (int i = 0; i < 4; i++)
#pragma unroll
        for (int j = 0; j < 8; j++) acc[i][j] = 0ull;
    float ksum = 0.f;

    // loader slots: j = t + 128k (k=0,1) -> row j>>4 (0..15), col j&15
    int rr[2], cc[2];
#pragma unroll
    for (int k = 0; k < 2; k++) { int j = t + 128 * k; rr[k] = j >> 4; cc[k] = j & 15; }

    float4 bk[2], bv[2];
#pragma unroll
    for (int k = 0; k < 2; k++) {
        size_t row = (size_t)(n * Ss + s0 + rr[k]);
        bk[k] = *(const float4*)(keys   + row * ROWSTRIDE + h * Dd + cc[k] * 4);
        bv[k] = *(const float4*)(values + row * ROWSTRIDE + h * Dd + cc[k] * 4);
    }
#pragma unroll
    for (int k = 0; k < 2; k++) {
        float4 f;
        f.x = featmap(bk[k].x); f.y = featmap(bk[k].y);
        f.z = featmap(bk[k].z); f.w = featmap(bk[k].w);
        *(float4*)&Ks[rr[k]][cc[k] * 4] = f;
        *(float4*)&Vs[rr[k]][cc[k] * 4] = bv[k];
    }
    __syncthreads();

    for (int tile = 0; tile < P1_NTILES; ++tile) {
        if (tile + 1 < P1_NTILES) {
#pragma unroll
            for (int k = 0; k < 2; k++) {
                size_t row = (size_t)(n * Ss + s0 + (tile + 1) * TS + rr[k]);
                bk[k] = *(const float4*)(keys   + row * ROWSTRIDE + h * Dd + cc[k] * 4);
                bv[k] = *(const float4*)(values + row * ROWSTRIDE + h * Dd + cc[k] * 4);
            }
        }
#pragma unroll
        for (int s2 = 0; s2 < 8; ++s2) {
            const int ss = g * 8 + s2;
            // K pairs natural (broadcast within warp by ty)
            ulonglong2 kpa = *(const ulonglong2*)&Ks[ss][ty * 8];
            ulonglong2 kpb = *(const ulonglong2*)&Ks[ss][ty * 8 + 4];
            float4 va = *(const float4*)&Vs[ss][tx * 4];
            float4 vb = *(const float4*)&Vs[ss][tx * 4 + 32];
            u64 kp[4] = { kpa.x, kpa.y, kpb.x, kpb.y };
            u64 vd[8] = { dup(va.x), dup(va.y), dup(va.z), dup(va.w),
                          dup(vb.x), dup(vb.y), dup(vb.z), dup(vb.w) };
#pragma unroll
            for (int dp = 0; dp < 4; ++dp)
#pragma unroll
                for (int e = 0; e < 8; ++e)
                    acc[dp][e] = ffma2(kp[dp], vd[e], acc[dp][e]);
        }
        // Ksum: each group's 64 threads sum column d=tg over its 8 ss
#pragma unroll
        for (int s2 = 0; s2 < 8; ++s2) ksum += Ks[g * 8 + s2][tg];
        __syncthreads();
        if (tile + 1 < P1_NTILES) {
#pragma unroll
            for (int k = 0; k < 2; k++) {
                float4 f;
                f.x = featmap(bk[k].x); f.y = featmap(bk[k].y);
                f.z = featmap(bk[k].z); f.w = featmap(bk[k].w);
                *(float4*)&Ks[rr[k]][cc[k] * 4] = f;
                *(float4*)&Vs[rr[k]][cc[k] * 4] = bv[k];
            }
            __syncthreads();
        }
    }

    // writeback: transposed partial [e][d]; d-pairs are contiguous
    const int slot = blockIdx.x * 2 + g;
    float* base = g_part_kv + ((size_t)slot * NH + nh) * 4096;
#pragma unroll
    for (int j = 0; j < 8; ++j) {
        const int e = (j < 4) ? (tx * 4 + j) : (tx * 4 + 28 + j);
        u64* row = (u64*)(base + e * 64 + ty * 8);
        *(ulonglong2*)(row)     = make_ulonglong2(acc[0][j], acc[1][j]);
        *(ulonglong2*)(row + 2) = make_ulonglong2(acc[2][j], acc[3][j]);
    }
    g_part_ks[(slot * NH + nh) * 64 + tg] = ksum;
}

// ============================================================================
// Phase 1b: fixed-order reduction over SLOTS partials
// ============================================================================
__global__ void reduce_kernel() {
    int i = blockIdx.x * 256 + threadIdx.x;
    if (i < NH * 1024) {                        // float4 units of KV
        float4 s = make_float4(0.f, 0.f, 0.f, 0.f);
#pragma unroll
        for (int c = 0; c < SLOTS; c++) {
            float4 p = *(const float4*)(g_part_kv + (size_t)c * NH * 4096 + i * 4);
            s.x += p.x; s.y += p.y; s.z += p.z; s.w += p.w;
        }
        *(float4*)(g_kv + i * 4) = s;
    } else if (i < NH * 1024 + NH * 64) {
        int j = i - NH * 1024;
        float s = 0.f;
#pragma unroll
        for (int c = 0; c < SLOTS; c++) s += g_part_ks[c * NH * 64 + j];
        g_ks[j] = s;
    }
}

// ============================================================================
// Phase 2. Block = 128 thr, tile 128l x 64e, thread 8l x 8e. Grid (Ll/128, NH).
// acc packed along l; Z is a 9th "e" column (b = dup(Ksum[d])).
// ============================================================================
__global__ __launch_bounds__(128, 3) void p2_kernel(const float* __restrict__ queries,
                                                    float* __restrict__ out) {
    __shared__ __align__(16) float KVs[64][68];  // [d][e]
    __shared__ __align__(16) float Ks1[64];
    __shared__ __align__(16) float Qd[8][132];   // [d_local][l] phi(Q), natural

    const int t  = threadIdx.x;
    const int nh = blockIdx.y;
    const int n  = nh >> 3, h = nh & 7;
    const int l0 = blockIdx.x * 128;
    const int ty = t >> 3;   // 0..15 -> l-base ty*8
    const int tx = t & 7;    // e in {tx*4..+3} u {tx*4+32..+35}

    // stage KV (transpose [e][d] -> [d][e]) and Ksum
    {
        const float* kvT = g_kv + (size_t)nh * 4096;
#pragma unroll
        for (int k = 0; k < 8; k++) {
            int idx = t + 128 * k;
            int e = idx >> 4, d4 = idx & 15;
            float4 p = *(const float4*)(kvT + e * 64 + d4 * 4);
            KVs[d4 * 4 + 0][e] = p.x;
            KVs[d4 * 4 + 1][e] = p.y;
            KVs[d4 * 4 + 2][e] = p.z;
            KVs[d4 * 4 + 3][e] = p.w;
        }
        if (t < 64) Ks1[t] = g_ks[nh * 64 + t];
    }

    u64 acc[4][8];              // [l-pair][e]
#pragma unroll
    for (int i = 0; i < 4; i++)
#pragma unroll
        for (int j = 0; j < 8; j++) acc[i][j] = 0ull;
    u64 z2[4] = { 0ull, 0ull, 0ull, 0ull };

    // Q chunk loaders: 128l x 8d = 256 float4; j = t + 128k -> l=j>>1, c=j&1
    int lr[2], lc[2];
#pragma unroll
    for (int k = 0; k < 2; k++) { int j = t + 128 * k; lr[k] = j >> 1; lc[k] = j & 1; }

    float4 bq[2];
#pragma unroll
    for (int k = 0; k < 2; k++) {
        size_t row = (size_t)(n * Ll + l0 + lr[k]);
        bq[k] = *(const float4*)(queries + row * ROWSTRIDE + h * Dd + lc[k] * 4);
    }
    __syncthreads();   // KV staging done; Qd about to be written
#pragma unroll
    for (int k = 0; k < 2; k++) {
        int db = lc[k] * 4, l = lr[k];
        Qd[db + 0][l] = featmap(bq[k].x);
        Qd[db + 1][l] = featmap(bq[k].y);
        Qd[db + 2][l] = featmap(bq[k].z);
        Qd[db + 3][l] = featmap(bq[k].w);
    }
    __syncthreads();

    for (int ch = 0; ch < 8; ++ch) {
        if (ch + 1 < 8) {
#pragma unroll
            for (int k = 0; k < 2; k++) {
                size_t row = (size_t)(n * Ll + l0 + lr[k]);
                bq[k] = *(const float4*)(queries + row * ROWSTRIDE + h * Dd +
                                         (ch + 1) * 8 + lc[k] * 4);
            }
        }
#pragma unroll
        for (int dd = 0; dd < 8; ++dd) {
            const int d = ch * 8 + dd;
            ulonglong2 qpa = *(const ulonglong2*)&Qd[dd][ty * 8];
            ulonglong2 qpb = *(const ulonglong2*)&Qd[dd][ty * 8 + 4];
            float4 va = *(const float4*)&KVs[d][tx * 4];
            float4 vb = *(const float4*)&KVs[d][tx * 4 + 32];
            float  ks = Ks1[d];
            u64 qp[4] = { qpa.x, qpa.y, qpb.x, qpb.y };
            u64 vd[8] = { dup(va.x), dup(va.y), dup(va.z), dup(va.w),
                          dup(vb.x), dup(vb.y), dup(vb.z), dup(vb.w) };
            u64 ksd = dup(ks);
#pragma unroll
            for (int lp = 0; lp < 4; ++lp) {
#pragma unroll
                for (int e = 0; e < 8; ++e)
                    acc[lp][e] = ffma2(qp[lp], vd[e], acc[lp][e]);
                z2[lp] = ffma2(qp[lp], ksd, z2[lp]);
            }
        }
        __syncthreads();
        if (ch + 1 < 8) {
#pragma unroll
            for (int k = 0; k < 2; k++) {
                int db = lc[k] * 4, l = lr[k];
                Qd[db + 0][l] = featmap(bq[k].x);
                Qd[db + 1][l] = featmap(bq[k].y);
                Qd[db + 2][l] = featmap(bq[k].z);
                Qd[db + 3][l] = featmap(bq[k].w);
            }
            __syncthreads();
        }
    }

    // epilogue: out = acc / (z + eps)
#pragma unroll
    for (int lp = 0; lp < 4; ++lp) {
        float zlo, zhi;
        upk2(z2[lp], zlo, zhi);
        float i0 = 1.0f / (zlo + 1e-6f);
        float i1 = 1.0f / (zhi + 1e-6f);
        float lo[8], hi[8];
#pragma unroll
        for (int e = 0; e < 8; ++e) upk2(acc[lp][e], lo[e], hi[e]);
        const int lA = l0 + ty * 8 + lp * 2;
        float* rA = out + ((size_t)(n * Ll + lA) * Hh + h) * Dd;
        float* rB = rA + ROWSTRIDE;   // lA+1
        *(float4*)(rA + tx * 4)      = make_float4(lo[0]*i0, lo[1]*i0, lo[2]*i0, lo[3]*i0);
        *(float4*)(rA + tx * 4 + 32) = make_float4(lo[4]*i0, lo[5]*i0, lo[6]*i0, lo[7]*i0);
        *(float4*)(rB + tx * 4)      = make_float4(hi[0]*i1, hi[1]*i1, hi[2]*i1, hi[3]*i1);
        *(float4*)(rB + tx * 4 + 32) = make_float4(hi[4]*i1, hi[5]*i1, hi[6]*i1, hi[7]*i1);
    }
}

// ============================================================================
extern "C" void kernel_launch(void* const* d_in, const int* in_sizes, int n_in,
                              void* d_out, int out_size) {
    const float* q = (const float*)d_in[0];
    const float* k = (const float*)d_in[1];
    const float* v = (const float*)d_in[2];
    float* o = (float*)d_out;
    (void)in_sizes; (void)n_in; (void)out_size;

    p1_kernel<<<dim3(P1_CHUNKS, NH), 128>>>(k, v);
    reduce_kernel<<<(NH * 1024 + NH * 64 + 255) / 256, 256>>>();
    p2_kernel<<<dim3(Ll / 128, NH), 128>>>(q, o);
}

// round 5
// speedup vs baseline: 1.4435x; 1.1011x over previous
#include <cuda_runtime.h>
#include <cuda_bf16.h>
#include <cstdint>

// LinearAttention: out[n,l,h,e] = (phi(Q)@KV) * Z, phi = elu+1 (vlen cancels)
//   KV = sum_s phi(K)[s,d] * V[s,e] ;  Z = 1/(phi(Q).Ksum + 1e-6)
//
// R5: phase 2 on warp-level mma.sync (HMMA bf16, sm_80+ -> compiles for
// sm_100 plain; tcgen05 is rejected by this harness's ptxas target).
// 2-term Dekker split (hi+lo bf16), 3 MMAs per tile accumulate in fp32.
// Z rides as B row 64 (N=72). Phase 1 unchanged (scalar FFMA2, 66us).

#define DEV_INLINE __device__ __forceinline__

constexpr int Hh = 8, Dd = 64, Ll = 8192, Ss = 8192, Nn = 4;
constexpr int NH = Nn * Hh;                // 32
constexpr int ROWSTRIDE = Hh * Dd;         // 512
constexpr int P1_CHUNKS = 32;
constexpr int P1_SCHUNK = Ss / P1_CHUNKS;  // 256
constexpr int TS = 16;
constexpr int P1_NTILES = P1_SCHUNK / TS;  // 16
constexpr int SLOTS = P1_CHUNKS * 2;       // 64

// scratch: KV partials TRANSPOSED [slot][nh][e][d]
__device__ __align__(16) float g_part_kv[(size_t)SLOTS * NH * 4096];
__device__ __align__(16) float g_part_ks[SLOTS * NH * 64];
__device__ __align__(16) float g_kv[NH * 4096];   // [nh][e][d]
__device__ __align__(16) float g_ks[NH * 64];

using u64 = unsigned long long;

DEV_INLINE u64 pk2(float lo, float hi) {
    u64 r; asm("mov.b64 %0,{%1,%2};" : "=l"(r) : "f"(lo), "f"(hi)); return r;
}
DEV_INLINE u64 ffma2(u64 a, u64 b, u64 c) {
    u64 d; asm("fma.rn.f32x2 %0,%1,%2,%3;" : "=l"(d) : "l"(a), "l"(b), "l"(c)); return d;
}
DEV_INLINE u64 dup(float x) { return pk2(x, x); }
DEV_INLINE float featmap(float x) { return __expf(fminf(x, 0.f)) + fmaxf(x, 0.f); }

// ============================================================================
// Phase 1 (unchanged from R3: 66.4us, scalar FFMA2)
// ============================================================================
__global__ __launch_bounds__(128, 3) void p1_kernel(const float* __restrict__ keys,
                                                    const float* __restrict__ values) {
    __shared__ __align__(16) float Ks[TS][68];
    __shared__ __align__(16) float Vs[TS][68];

    const int t  = threadIdx.x;
    const int nh = blockIdx.y;
    const int n  = nh >> 3, h = nh & 7;
    const int s0 = blockIdx.x * P1_SCHUNK;
    const int g  = t >> 6;
    const int tg = t & 63;
    const int ty = tg >> 3;
    const int tx = tg & 7;

    u64 acc[4][8];
#pragma unroll
    for (int i = 0; i < 4; i++)
#pragma unroll
        for (int j = 0; j < 8; j++) acc[i][j] = 0ull;
    float ksum = 0.f;

    int rr[2], cc[2];
#pragma unroll
    for (int k = 0; k < 2; k++) { int j = t + 128 * k; rr[k] = j >> 4; cc[k] = j & 15; }

    float4 bk[2], bv[2];
#pragma unroll
    for (int k = 0; k < 2; k++) {
        size_t row = (size_t)(n * Ss + s0 + rr[k]);
        bk[k] = *(const float4*)(keys   + row * ROWSTRIDE + h * Dd + cc[k] * 4);
        bv[k] = *(const float4*)(values + row * ROWSTRIDE + h * Dd + cc[k] * 4);
    }
#pragma unroll
    for (int k = 0; k < 2; k++) {
        float4 f;
        f.x = featmap(bk[k].x); f.y = featmap(bk[k].y);
        f.z = featmap(bk[k].z); f.w = featmap(bk[k].w);
        *(float4*)&Ks[rr[k]][cc[k] * 4] = f;
        *(float4*)&Vs[rr[k]][cc[k] * 4] = bv[k];
    }
    __syncthreads();

    for (int tile = 0; tile < P1_NTILES; ++tile) {
        if (tile + 1 < P1_NTILES) {
#pragma unroll
            for (int k = 0; k < 2; k++) {
                size_t row = (size_t)(n * Ss + s0 + (tile + 1) * TS + rr[k]);
                bk[k] = *(const float4*)(keys   + row * ROWSTRIDE + h * Dd + cc[k] * 4);
                bv[k] = *(const float4*)(values + row * ROWSTRIDE + h * Dd + cc[k] * 4);
            }
        }
#pragma unroll
        for (int s2 = 0; s2 < 8; ++s2) {
            const int ss = g * 8 + s2;
            ulonglong2 kpa = *(const ulonglong2*)&Ks[ss][ty * 8];
            ulonglong2 kpb = *(const ulonglong2*)&Ks[ss][ty * 8 + 4];
            float4 va = *(const float4*)&Vs[ss][tx * 4];
            float4 vb = *(const float4*)&Vs[ss][tx * 4 + 32];
            u64 kp[4] = { kpa.x, kpa.y, kpb.x, kpb.y };
            u64 vd[8] = { dup(va.x), dup(va.y), dup(va.z), dup(va.w),
                          dup(vb.x), dup(vb.y), dup(vb.z), dup(vb.w) };
#pragma unroll
            for (int dp = 0; dp < 4; ++dp)
#pragma unroll
                for (int e = 0; e < 8; ++e)
                    acc[dp][e] = ffma2(kp[dp], vd[e], acc[dp][e]);
        }
#pragma unroll
        for (int s2 = 0; s2 < 8; ++s2) ksum += Ks[g * 8 + s2][tg];
        __syncthreads();
        if (tile + 1 < P1_NTILES) {
#pragma unroll
            for (int k = 0; k < 2; k++) {
                float4 f;
                f.x = featmap(bk[k].x); f.y = featmap(bk[k].y);
                f.z = featmap(bk[k].z); f.w = featmap(bk[k].w);
                *(float4*)&Ks[rr[k]][cc[k] * 4] = f;
                *(float4*)&Vs[rr[k]][cc[k] * 4] = bv[k];
            }
            __syncthreads();
        }
    }

    const int slot = blockIdx.x * 2 + g;
    float* base = g_part_kv + ((size_t)slot * NH + nh) * 4096;
#pragma unroll
    for (int j = 0; j < 8; ++j) {
        const int e = (j < 4) ? (tx * 4 + j) : (tx * 4 + 28 + j);
        u64* row = (u64*)(base + e * 64 + ty * 8);
        *(ulonglong2*)(row)     = make_ulonglong2(acc[0][j], acc[1][j]);
        *(ulonglong2*)(row + 2) = make_ulonglong2(acc[2][j], acc[3][j]);
    }
    g_part_ks[(slot * NH + nh) * 64 + tg] = ksum;
}

// ============================================================================
// Phase 1b (unchanged)
// ============================================================================
__global__ void reduce_kernel() {
    int i = blockIdx.x * 256 + threadIdx.x;
    if (i < NH * 1024) {
        float4 s = make_float4(0.f, 0.f, 0.f, 0.f);
#pragma unroll
        for (int c = 0; c < SLOTS; c++) {
            float4 p = *(const float4*)(g_part_kv + (size_t)c * NH * 4096 + i * 4);
            s.x += p.x; s.y += p.y; s.z += p.z; s.w += p.w;
        }
        *(float4*)(g_kv + i * 4) = s;
    } else if (i < NH * 1024 + NH * 64) {
        int j = i - NH * 1024;
        float s = 0.f;
#pragma unroll
        for (int c = 0; c < SLOTS; c++) s += g_part_ks[c * NH * 64 + j];
        g_ks[j] = s;
    }
}

// ============================================================================
// Phase 2: warp-level mma.sync bf16 (m16n8k16), 2-term Dekker split.
// ============================================================================
DEV_INLINE void mma_bf16(float4& c, const uint32_t a[4], uint32_t b0, uint32_t b1) {
    asm volatile(
        "mma.sync.aligned.m16n8k16.row.col.f32.bf16.bf16.f32 "
        "{%0,%1,%2,%3}, {%4,%5,%6,%7}, {%8,%9}, {%0,%1,%2,%3};"
        : "+f"(c.x), "+f"(c.y), "+f"(c.z), "+f"(c.w)
        : "r"(a[0]), "r"(a[1]), "r"(a[2]), "r"(a[3]), "r"(b0), "r"(b1));
}
DEV_INLINE unsigned bf2u(__nv_bfloat162 v) { return *reinterpret_cast<unsigned*>(&v); }
// Dekker split of (a,b) -> bf16x2 hi word + lo word
DEV_INLINE void bsplit2(float a, float b, unsigned& h, unsigned& l) {
    __nv_bfloat162 hv = __floats2bfloat162_rn(a, b);
    float2 hf = __bfloat1622float2(hv);
    __nv_bfloat162 lv = __floats2bfloat162_rn(a - hf.x, b - hf.y);
    h = bf2u(hv); l = bf2u(lv);
}

// smem layout (dynamic): padded rows of 144 B (72 bf16) -> 4-bank row shift
// makes all quad-pattern fragment LDS.32 conflict-free.
constexpr uint32_t QH_OFF = 0;          // 128 rows x 144 B
constexpr uint32_t QL_OFF = 18432;
constexpr uint32_t BH_OFF = 36864;      // 72 rows x 144 B
constexpr uint32_t BL_OFF = 47232;
constexpr uint32_t P2_DSM = 57600;

__global__ __launch_bounds__(128) void p2_kernel(const float* __restrict__ queries,
                                                 float* __restrict__ out) {
    extern __shared__ __align__(16) char sm[];
    char* QH = sm + QH_OFF; char* QL = sm + QL_OFF;
    char* BH = sm + BH_OFF; char* BL = sm + BL_OFF;

    const int t    = threadIdx.x;
    const int wid  = t >> 5, lane = t & 31;
    const int g    = lane >> 2, tg = lane & 3;   // mma group / thread-in-group
    const int nh   = blockIdx.y;
    const int n    = nh >> 3, h = nh & 7;
    const int l0   = blockIdx.x * 128;

    // ---- stage B: rows 0..63 = KV[e][d], row 64 = Ksum[d], 65..71 = 0 ----
    if (t < 72) {
        const float* src = (t < 64) ? (g_kv + (size_t)nh * 4096 + t * 64)
                                    : (g_ks + nh * 64);
#pragma unroll
        for (int c4 = 0; c4 < 16; ++c4) {
            float4 v = (t <= 64) ? *(const float4*)(src + c4 * 4)
                                 : make_float4(0.f, 0.f, 0.f, 0.f);
            unsigned hxy, lxy, hzw, lzw;
            bsplit2(v.x, v.y, hxy, lxy);
            bsplit2(v.z, v.w, hzw, lzw);
            *(u64*)(BH + t * 144 + c4 * 8) = ((u64)hzw << 32) | hxy;
            *(u64*)(BL + t * 144 + c4 * 8) = ((u64)lzw << 32) | lxy;
        }
    }

    // ---- stage Q: 128 rows x 64 cols, phi + split ----
    const float* qbase = queries + ((size_t)(n * Ll + l0) * ROWSTRIDE + h * Dd);
#pragma unroll
    for (int k2 = 0; k2 < 16; ++k2) {
        int idx = t + 128 * k2;
        int row = idx >> 4, c4 = idx & 15;
        float4 qv = *(const float4*)(qbase + (size_t)row * ROWSTRIDE + c4 * 4);
        float fx = featmap(qv.x), fy = featmap(qv.y);
        float fz = featmap(qv.z), fw = featmap(qv.w);
        unsigned hxy, lxy, hzw, lzw;
        bsplit2(fx, fy, hxy, lxy);
        bsplit2(fz, fw, hzw, lzw);
        *(u64*)(QH + row * 144 + c4 * 8) = ((u64)hzw << 32) | hxy;
        *(u64*)(QL + row * 144 + c4 * 8) = ((u64)lzw << 32) | lxy;
    }
    __syncthreads();

    // ---- MMA mainloop: warp owns rows [wid*32, wid*32+32), 9 n-tiles ----
    float4 C[2][9];
#pragma unroll
    for (int mt = 0; mt < 2; ++mt)
#pragma unroll
        for (int nt = 0; nt < 9; ++nt) C[mt][nt] = make_float4(0.f, 0.f, 0.f, 0.f);

    const int cb = tg * 4;   // byte offset of d = tg*2 within a row (+ k0*2)
#pragma unroll
    for (int kt = 0; kt < 4; ++kt) {
        const int kb = kt * 32 + cb;   // (k0 + tg*2) * 2 bytes
        uint32_t ah[2][4], al[2][4];
#pragma unroll
        for (int mt = 0; mt < 2; ++mt) {
            const int r0 = wid * 32 + mt * 16 + g;
            ah[mt][0] = *(const uint32_t*)(QH + r0 * 144 + kb);
            ah[mt][1] = *(const uint32_t*)(QH + (r0 + 8) * 144 + kb);
            ah[mt][2] = *(const uint32_t*)(QH + r0 * 144 + kb + 16);
            ah[mt][3] = *(const uint32_t*)(QH + (r0 + 8) * 144 + kb + 16);
            al[mt][0] = *(const uint32_t*)(QL + r0 * 144 + kb);
            al[mt][1] = *(const uint32_t*)(QL + (r0 + 8) * 144 + kb);
            al[mt][2] = *(const uint32_t*)(QL + r0 * 144 + kb + 16);
            al[mt][3] = *(const uint32_t*)(QL + (r0 + 8) * 144 + kb + 16);
        }
#pragma unroll
        for (int nt = 0; nt < 9; ++nt) {
            const int e0 = nt * 8 + g;
            uint32_t bh0 = *(const uint32_t*)(BH + e0 * 144 + kb);
            uint32_t bh1 = *(const uint32_t*)(BH + e0 * 144 + kb + 16);
            uint32_t bl0 = *(const uint32_t*)(BL + e0 * 144 + kb);
            uint32_t bl1 = *(const uint32_t*)(BL + e0 * 144 + kb + 16);
#pragma unroll
            for (int mt = 0; mt < 2; ++mt) {
                mma_bf16(C[mt][nt], ah[mt], bh0, bh1);
                mma_bf16(C[mt][nt], ah[mt], bl0, bl1);
                mma_bf16(C[mt][nt], al[mt], bh0, bh1);
            }
        }
    }

    // ---- epilogue: Z = D[:,64] (n-tile 8, col 0 -> tg==0 lanes) ----
#pragma unroll
    for (int mt = 0; mt < 2; ++mt) {
        const int src = (lane >> 2) << 2;   // quad leader
        float z0 = __shfl_sync(0xFFFFFFFFu, C[mt][8].x, src);
        float z1 = __shfl_sync(0xFFFFFFFFu, C[mt][8].z, src);
        float i0 = 1.0f / (z0 + 1e-6f);
        float i1 = 1.0f / (z1 + 1e-6f);
        const int r0 = l0 + wid * 32 + mt * 16 + g;
        float* p0 = out + ((size_t)(n * Ll + r0) * Hh + h) * Dd;
        float* p1 = p0 + (size_t)8 * ROWSTRIDE;
#pragma unroll
        for (int nt = 0; nt < 8; ++nt) {
            const int col = nt * 8 + tg * 2;
            *(float2*)(p0 + col) = make_float2(C[mt][nt].x * i0, C[mt][nt].y * i0);
            *(float2*)(p1 + col) = make_float2(C[mt][nt].z * i1, C[mt][nt].w * i1);
        }
    }
}

// ============================================================================
extern "C" void kernel_launch(void* const* d_in, const int* in_sizes, int n_in,
                              void* d_out, int out_size) {
    const float* q = (const float*)d_in[0];
    const float* k = (const float*)d_in[1];
    const float* v = (const float*)d_in[2];
    float* o = (float*)d_out;
    (void)in_sizes; (void)n_in; (void)out_size;

    cudaFuncSetAttribute(p2_kernel, cudaFuncAttributeMaxDynamicSharedMemorySize, P2_DSM);

    p1_kernel<<<dim3(P1_CHUNKS, NH), 128>>>(k, v);
    reduce_kernel<<<(NH * 1024 + NH * 64 + 255) / 256, 256>>>();
    p2_kernel<<<dim3(Ll / 128, NH), 128, P2_DSM>>>(q, o);
}